// round 15
// baseline (speedup 1.0000x reference)
#include <cuda_runtime.h>
#include <cuda_bf16.h>
#include <cuda_fp16.h>
#include <math.h>
#include <stdint.h>

#define BATCH 2
#define SEQ   2048
#define DIM   1024
#define HEADS 16
#define HDIM  64
#define NTOK  (BATCH*SEQ)          // 4096
#define QKV_N (3*DIM)              // 3072

typedef unsigned long long u64;

// 0.125 * log2(e): folds attention scale + base-2 softmax into q
#define S0F 0.18033688011112042f

// ---- helpers (all base-PTX, no 'a' features) --------------------------------
__device__ __forceinline__ uint32_t s2u32(const void* p) {
    uint32_t a;
    asm("{ .reg .u64 t; cvta.to.shared.u64 t, %1; cvt.u32.u64 %0, t; }" : "=r"(a) : "l"(p));
    return a;
}
__device__ __forceinline__ void ldsm_x4(uint32_t* r, uint32_t addr) {
    asm volatile("ldmatrix.sync.aligned.m8n8.x4.shared.b16 {%0,%1,%2,%3}, [%4];"
                 : "=r"(r[0]), "=r"(r[1]), "=r"(r[2]), "=r"(r[3]) : "r"(addr));
}
__device__ __forceinline__ void ldsm_x4_t(uint32_t* r, uint32_t addr) {
    asm volatile("ldmatrix.sync.aligned.m8n8.x4.trans.shared.b16 {%0,%1,%2,%3}, [%4];"
                 : "=r"(r[0]), "=r"(r[1]), "=r"(r[2]), "=r"(r[3]) : "r"(addr));
}
__device__ __forceinline__ void mma_f16(float* c, const uint32_t* a, const uint32_t* b) {
    asm volatile(
        "mma.sync.aligned.m16n8k16.row.col.f32.f16.f16.f32 "
        "{%0,%1,%2,%3},{%4,%5,%6,%7},{%8,%9},{%0,%1,%2,%3};"
        : "+f"(c[0]), "+f"(c[1]), "+f"(c[2]), "+f"(c[3])
        : "r"(a[0]), "r"(a[1]), "r"(a[2]), "r"(a[3]), "r"(b[0]), "r"(b[1]));
}
__device__ __forceinline__ void cpa16(uint32_t dst, const void* src) {
    asm volatile("cp.async.cg.shared.global [%0], [%1], 16;" :: "r"(dst), "l"(src) : "memory");
}
#define CP_COMMIT() asm volatile("cp.async.commit_group;" ::: "memory")
#define CP_WAIT(n)  asm volatile("cp.async.wait_group %0;" :: "n"(n) : "memory")

__device__ __forceinline__ float ex2f(float x) {
    float r; asm("ex2.approx.f32 %0, %1;" : "=f"(r) : "f"(x)); return r;
}
__device__ __forceinline__ uint32_t hf2u(__half a, __half b) {
    __half2 t = __halves2half2(a, b);
    return *(uint32_t*)&t;
}

// SW64 swizzle for 64-byte rows (GEMM tiles, BK=32)
__device__ __forceinline__ uint32_t swzoff(int row, int kb) {
    return (uint32_t)(row * 64 + (kb ^ ((row & 6) << 3)));
}
// swizzle for 128-byte rows (attention tiles, 64 elems/row)
__device__ __forceinline__ uint32_t swz128(int row, int cb) {
    return (uint32_t)(row * 128 + (cb ^ ((row & 7) << 4)));
}

// ---- device scratch ----------------------------------------------------------
__device__ float g_cos[SEQ*32];
__device__ float g_sin[SEQ*32];
__device__ __half g_xf[NTOK*DIM];                          // fp16(X)
__device__ __half g_wqT[QKV_N*DIM];                        // fp16(W_qkv^T) (N,K)
__device__ __half g_woT[DIM*DIM];                          // fp16(W_out^T) (N,K)
__device__ __half g_qhi[BATCH*HEADS*SEQ*HDIM], g_qlo[BATCH*HEADS*SEQ*HDIM];
__device__ __half g_kf[BATCH*HEADS*SEQ*HDIM];              // single fp16 K
__device__ __half g_vf[BATCH*HEADS*SEQ*HDIM];              // single fp16 V
__device__ __half g_af[NTOK*DIM];                          // single fp16 attn out

// ---------------------------------------------------------------------------
// RoPE table (fp64 sincos for accuracy)
// ---------------------------------------------------------------------------
__global__ void rope_table_kernel() {
    int idx = blockIdx.x * blockDim.x + threadIdx.x;
    if (idx >= SEQ * 32) return;
    int s = idx >> 5;
    int j = idx & 31;
    double theta = (double)s * pow(10000.0, -(double)j / 32.0);
    double sc, cc;
    sincos(theta, &sc, &cc);
    g_cos[idx] = (float)cc;
    g_sin[idx] = (float)sc;
}

// ---------------------------------------------------------------------------
// Convert X (fp32) -> single fp16
// ---------------------------------------------------------------------------
__global__ __launch_bounds__(256) void convert_x_kernel(const float* __restrict__ X) {
    int i = (blockIdx.x * 256 + threadIdx.x) * 4;
    float4 v = *(const float4*)(X + i);
    *(uint32_t*)(g_xf + i)     = hf2u(__float2half(v.x), __float2half(v.y));
    *(uint32_t*)(g_xf + i + 2) = hf2u(__float2half(v.z), __float2half(v.w));
}

// ---------------------------------------------------------------------------
// Transpose BOTH weights in one launch: blockIdx.x < 96 -> W_qkv, else W_out.
// ---------------------------------------------------------------------------
__global__ void transpose_f16_kernel(const float* __restrict__ Wq,
                                     const float* __restrict__ Wo) {
    __shared__ float t32[32][33];
    const int which = (blockIdx.x >= QKV_N / 32);
    const int bx = which ? (blockIdx.x - QKV_N / 32) : blockIdx.x;
    const int N = which ? DIM : QKV_N;
    const float* W = which ? Wo : Wq;
    __half* T = which ? g_woT : g_wqT;
    const int n0 = bx * 32, k0 = blockIdx.y * 32;
    const int tx = threadIdx.x, ty = threadIdx.y;       // (32, 8)
#pragma unroll
    for (int i = 0; i < 4; i++)
        t32[ty + 8 * i][tx] = W[(size_t)(k0 + ty + 8 * i) * N + n0 + tx];
    __syncthreads();
#pragma unroll
    for (int i = 0; i < 4; i++) {
        float v = t32[tx][ty + 8 * i];
        T[(size_t)(n0 + ty + 8 * i) * DIM + k0 + tx] = __float2half(v);
    }
}

// ---------------------------------------------------------------------------
// Warp-MMA fp16 GEMM (R11 frozen config): CTA 128x128, 8 warps (2x4),
// warp tile 64x32, BK=32, 4-stage cp.async, one sync per chunk, 2 CTAs/SM.
// MODE 0: fp16(X) @ W_qkv + bias, RoPE -> q split fp16 (scaled), k/v fp16
// MODE 1: fp16(attn) @ W_out + bias -> outp (fp32)
// ---------------------------------------------------------------------------
#define OFF_B   8192
#define BUF_SZ  16384
#define GSMEM   69632             // max(4*BUF_SZ=64K, 128*132*4=67.6K staging)

template<int MODE>
__global__ __launch_bounds__(256, 2) void mma_gemm_kernel(const float* __restrict__ bias,
                                                          float* __restrict__ outp) {
    extern __shared__ __align__(16) char sm[];
    const uint32_t smb = s2u32(sm);
    const int tid  = threadIdx.x;
    const int wid  = tid >> 5;
    const int lane = tid & 31;
    const int warp_m = wid >> 2;     // 0..1
    const int warp_n = wid & 3;      // 0..3

    const int n0 = blockIdx.x * 128;
    const int m0 = blockIdx.y * 128;

    const __half* __restrict__ Ah = (MODE == 0) ? g_xf : g_af;
    const __half* __restrict__ Bw = (MODE == 0) ? g_wqT : g_woT;

    float c[4][4][4];
#pragma unroll
    for (int i = 0; i < 4; i++)
#pragma unroll
        for (int j = 0; j < 4; j++)
#pragma unroll
            for (int r = 0; r < 4; r++) c[i][j][r] = 0.0f;

    const int ld_row = tid >> 2;          // 0..63
    const int ld_kb  = (tid & 3) * 16;

#define ISSUE_CHUNK(chunk, buf) do {                                           \
    const int k0e = (chunk) * 32;                                              \
    const uint32_t bb = smb + (buf) * BUF_SZ;                                  \
    _Pragma("unroll")                                                          \
    for (int m = 0; m < 2; m++) {                                              \
        const int row = ld_row + m * 64;                                       \
        const uint32_t so = swzoff(row, ld_kb);                                \
        cpa16(bb + so,         (const char*)(Ah + (size_t)(m0 + row) * DIM + k0e) + ld_kb); \
        cpa16(bb + OFF_B + so, (const char*)(Bw + (size_t)(n0 + row) * DIM + k0e) + ld_kb); \
    }                                                                          \
} while (0)

    ISSUE_CHUNK(0, 0); CP_COMMIT();
    ISSUE_CHUNK(1, 1); CP_COMMIT();
    ISSUE_CHUNK(2, 2); CP_COMMIT();

    for (int ch = 0; ch < 32; ch++) {
        if (ch <= 29) { CP_WAIT(2); }
        else if (ch == 30) { CP_WAIT(1); }
        else { CP_WAIT(0); }
        __syncthreads();
        if (ch + 3 < 32) {
            ISSUE_CHUNK(ch + 3, (ch + 3) & 3);
            CP_COMMIT();
        }

        const uint32_t bb = smb + (ch & 3) * BUF_SZ;
#pragma unroll
        for (int ks = 0; ks < 2; ks++) {
            uint32_t ah[4][4];
#pragma unroll
            for (int i = 0; i < 4; i++) {
                const int row = warp_m * 64 + 16 * i + (lane & 7) + ((lane >> 3) & 1) * 8;
                const int kb  = ks * 32 + (lane >> 4) * 16;
                ldsm_x4(ah[i], bb + swzoff(row, kb));
            }
            uint32_t bf[4][2];
#pragma unroll
            for (int j2 = 0; j2 < 2; j2++) {
                const int row = warp_n * 32 + 16 * j2 + (lane & 7) + ((lane >> 4) & 1) * 8;
                const int kb  = ks * 32 + ((lane >> 3) & 1) * 16;
                uint32_t r[4];
                ldsm_x4(r, bb + OFF_B + swzoff(row, kb));
                bf[2 * j2][0] = r[0]; bf[2 * j2][1] = r[1];
                bf[2 * j2 + 1][0] = r[2]; bf[2 * j2 + 1][1] = r[3];
            }
#pragma unroll
            for (int i = 0; i < 4; i++)
#pragma unroll
                for (int j = 0; j < 4; j++)
                    mma_f16(c[i][j], ah[i], bf[j]);
        }
    }
#undef ISSUE_CHUNK

    if (MODE == 1) {
#pragma unroll
        for (int i = 0; i < 4; i++) {
            const int row = m0 + warp_m * 64 + 16 * i + (lane >> 2);
#pragma unroll
            for (int j = 0; j < 4; j++) {
                const int col = n0 + warp_n * 32 + 8 * j + (lane & 3) * 2;
                const float b0 = bias[col], b1 = bias[col + 1];
                float2 v0 = make_float2(c[i][j][0] + b0, c[i][j][1] + b1);
                float2 v1 = make_float2(c[i][j][2] + b0, c[i][j][3] + b1);
                *(float2*)&outp[(size_t)row * DIM + col]       = v0;
                *(float2*)&outp[(size_t)(row + 8) * DIM + col] = v1;
            }
        }
        return;
    }

    // MODE 0: stage to smem so RoPE pairs (d, d+32) are in one thread
    __syncthreads();
    float* st = (float*)sm;                 // 128 rows x 132 stride
#pragma unroll
    for (int i = 0; i < 4; i++) {
        const int rl = warp_m * 64 + 16 * i + (lane >> 2);
#pragma unroll
        for (int j = 0; j < 4; j++) {
            const int cl = warp_n * 32 + 8 * j + (lane & 3) * 2;
            st[rl * 132 + cl]           = c[i][j][0];
            st[rl * 132 + cl + 1]       = c[i][j][1];
            st[(rl + 8) * 132 + cl]     = c[i][j][2];
            st[(rl + 8) * 132 + cl + 1] = c[i][j][3];
        }
    }
    __syncthreads();

    const int comp = n0 >> 10;               // 0=q 1=k 2=v
    const int r  = tid >> 1;
    const int hl = tid & 1;
    const int token = m0 + r;
    const int s  = token & (SEQ - 1);
    const int bb2 = token >> 11;
    const int gh = ((n0 + hl * 64) >> 6) & (HEADS - 1);
    const float* brow = bias + n0 + hl * 64;
    const float* srow = st + r * 132 + hl * 64;

    float vals[64];
    if (comp < 2) {
#pragma unroll
        for (int d = 0; d < 32; d++) {
            float x1 = srow[d]      + brow[d];
            float x2 = srow[32 + d] + brow[32 + d];
            float cs = g_cos[s * 32 + d], sn = g_sin[s * 32 + d];
            vals[d]      = x1 * cs - x2 * sn;
            vals[d + 32] = x2 * cs + x1 * sn;
        }
        if (comp == 0) {
#pragma unroll
            for (int j = 0; j < 64; j++) vals[j] *= S0F;
        }
    } else {
#pragma unroll
        for (int j = 0; j < 64; j++) vals[j] = srow[j] + brow[j];
    }

    const size_t base = (((size_t)bb2 * HEADS + gh) * SEQ + s) * HDIM;
    if (comp == 0) {
#pragma unroll
        for (int j2 = 0; j2 < 32; j2++) {
            float v0 = vals[2 * j2], v1 = vals[2 * j2 + 1];
            __half h0 = __float2half(v0), h1 = __float2half(v1);
            __half l0 = __float2half(v0 - __half2float(h0));
            __half l1 = __float2half(v1 - __half2float(h1));
            *(uint32_t*)(g_qhi + base + 2 * j2) = hf2u(h0, h1);
            *(uint32_t*)(g_qlo + base + 2 * j2) = hf2u(l0, l1);
        }
    } else {
        __half* df = (comp == 1) ? g_kf : g_vf;
#pragma unroll
        for (int j2 = 0; j2 < 32; j2++)
            *(uint32_t*)(df + base + 2 * j2) =
                hf2u(__float2half(vals[2 * j2]), __float2half(vals[2 * j2 + 1]));
    }
}

// ---------------------------------------------------------------------------
// MMA flash attention (R11 shape + 3-buffer KV pipeline, lookahead 2):
// grid (BH=32, QT=16), 128 threads (4 warps x 32 q-rows). 32-key tiles;
// QK = (qh+ql) x k_fp16; PV = (ph+pl) x v_fp16; base-2 softmax; causal;
// longest-first qt. Single fp16 output.
// smem: [0,16K) Qhi, [16K,32K) Qlo, bufs at 32K+b*8K (b=0..2): K +0, V +4096.
// ---------------------------------------------------------------------------
#define ATTN_SMEM 57344

__global__ __launch_bounds__(128) void attn_mma_kernel() {
    extern __shared__ __align__(16) char sm[];
    const uint32_t smb = s2u32(sm);
    const int bh = blockIdx.x;
    const int qt = (SEQ / 128 - 1) - blockIdx.y;     // longest-first scheduling
    const int tid = threadIdx.x, wid = tid >> 5, lane = tid & 31;
    const int gid = lane >> 2, tq = lane & 3;

    const __half* Qh = g_qhi + (size_t)bh * SEQ * HDIM;
    const __half* Ql = g_qlo + (size_t)bh * SEQ * HDIM;
    const __half* Kf = g_kf  + (size_t)bh * SEQ * HDIM;
    const __half* Vf = g_vf  + (size_t)bh * SEQ * HDIM;

    {
        const char* sh = (const char*)(Qh + (size_t)(qt * 128 + tid) * HDIM);
        const char* sl = (const char*)(Ql + (size_t)(qt * 128 + tid) * HDIM);
#pragma unroll
        for (int i = 0; i < 8; i++) {
            const uint32_t off = swz128(tid, i * 16);
            cpa16(smb + off, sh + i * 16);
            cpa16(smb + 16384 + off, sl + i * 16);
        }
    }
    CP_COMMIT();

    const int NT = 4 * qt + 4;

#define ISSUE_KV(t, b) do {                                                     \
    const int k0i = (t) * 32;                                                   \
    const uint32_t kb = smb + 32768 + (b) * 8192;                               \
    _Pragma("unroll")                                                           \
    for (int i = 0; i < 2; i++) {                                               \
        const int j = tid * 2 + i;                                              \
        const int rw = j >> 3, cbb = (j & 7) * 16;                              \
        const uint32_t off = swz128(rw, cbb);                                   \
        cpa16(kb + off,        (const char*)(Kf + (size_t)(k0i + rw) * HDIM) + cbb); \
        cpa16(kb + 4096 + off, (const char*)(Vf + (size_t)(k0i + rw) * HDIM) + cbb); \
    }                                                                           \
} while (0)

    ISSUE_KV(0, 0); CP_COMMIT();
    ISSUE_KV(1, 1); CP_COMMIT();          // NT >= 4 always

    float c_o[2][8][4];
#pragma unroll
    for (int m = 0; m < 2; m++)
#pragma unroll
        for (int n = 0; n < 8; n++)
#pragma unroll
            for (int r = 0; r < 4; r++) c_o[m][n][r] = 0.0f;
    float m_s[2][2] = {{-1e30f, -1e30f}, {-1e30f, -1e30f}};
    float l_s[2][2] = {{0.0f, 0.0f}, {0.0f, 0.0f}};

    for (int t = 0; t < NT; t++) {
        if (t + 1 < NT) { CP_WAIT(1); } else { CP_WAIT(0); }
        __syncthreads();
        if (t + 2 < NT) {
            ISSUE_KV(t + 2, (t + 2) % 3);
            CP_COMMIT();
        }

        const bool active = (t <= 4 * qt + wid);
        if (active) {
            const uint32_t kvb = smb + 32768 + (t % 3) * 8192;

            float c_s[2][4][4];
#pragma unroll
            for (int m = 0; m < 2; m++)
#pragma unroll
                for (int n = 0; n < 4; n++)
#pragma unroll
                    for (int r = 0; r < 4; r++) c_s[m][n][r] = 0.0f;

#pragma unroll
            for (int ks = 0; ks < 4; ks++) {
                uint32_t qa[2][4], qb[2][4];
#pragma unroll
                for (int m = 0; m < 2; m++) {
                    const uint32_t off = swz128(
                        wid * 32 + m * 16 + (lane & 7) + ((lane >> 3) & 1) * 8,
                        ks * 32 + ((lane >> 4) & 1) * 16);
                    ldsm_x4(qa[m], smb + off);
                    ldsm_x4(qb[m], smb + 16384 + off);
                }
                uint32_t kf[4][2];
#pragma unroll
                for (int jj = 0; jj < 2; jj++) {
                    const uint32_t off = swz128(
                        16 * jj + (lane & 7) + ((lane >> 4) & 1) * 8,
                        ks * 32 + ((lane >> 3) & 1) * 16);
                    uint32_t r[4];
                    ldsm_x4(r, kvb + off);
                    kf[2 * jj][0] = r[0]; kf[2 * jj][1] = r[1];
                    kf[2 * jj + 1][0] = r[2]; kf[2 * jj + 1][1] = r[3];
                }
#pragma unroll
                for (int m = 0; m < 2; m++)
#pragma unroll
                    for (int n = 0; n < 4; n++) {
                        mma_f16(c_s[m][n], qa[m], kf[n]);
                        mma_f16(c_s[m][n], qb[m], kf[n]);
                    }
            }

            if (t == 4 * qt + wid) {
                const int k0 = t * 32;
                const int rbase = qt * 128 + wid * 32;
#pragma unroll
                for (int m = 0; m < 2; m++) {
                    const int r0 = rbase + m * 16 + gid, r1 = r0 + 8;
#pragma unroll
                    for (int n = 0; n < 4; n++) {
                        const int key = k0 + 8 * n + 2 * tq;
                        if (key     > r0) c_s[m][n][0] = -1e30f;
                        if (key + 1 > r0) c_s[m][n][1] = -1e30f;
                        if (key     > r1) c_s[m][n][2] = -1e30f;
                        if (key + 1 > r1) c_s[m][n][3] = -1e30f;
                    }
                }
            }

            uint32_t aph[2][2][4], apl[2][2][4];
#pragma unroll
            for (int m = 0; m < 2; m++) {
                float mx0 = -1e30f, mx1 = -1e30f;
#pragma unroll
                for (int n = 0; n < 4; n++) {
                    mx0 = fmaxf(mx0, fmaxf(c_s[m][n][0], c_s[m][n][1]));
                    mx1 = fmaxf(mx1, fmaxf(c_s[m][n][2], c_s[m][n][3]));
                }
                mx0 = fmaxf(mx0, __shfl_xor_sync(0xffffffffu, mx0, 1));
                mx0 = fmaxf(mx0, __shfl_xor_sync(0xffffffffu, mx0, 2));
                mx1 = fmaxf(mx1, __shfl_xor_sync(0xffffffffu, mx1, 1));
                mx1 = fmaxf(mx1, __shfl_xor_sync(0xffffffffu, mx1, 2));
                const float mn0 = fmaxf(m_s[m][0], mx0);
                const float mn1 = fmaxf(m_s[m][1], mx1);
                const float cr0 = ex2f(m_s[m][0] - mn0);
                const float cr1 = ex2f(m_s[m][1] - mn1);
                m_s[m][0] = mn0; m_s[m][1] = mn1;
                float s0 = 0.0f, s1 = 0.0f;
#pragma unroll
                for (int n = 0; n < 4; n++) {
                    const float p0 = ex2f(c_s[m][n][0] - mn0);
                    const float p1 = ex2f(c_s[m][n][1] - mn0);
                    const float p2 = ex2f(c_s[m][n][2] - mn1);
                    const float p3 = ex2f(c_s[m][n][3] - mn1);
                    s0 += p0 + p1; s1 += p2 + p3;
                    const __half h0 = __float2half(p0), h1 = __float2half(p1);
                    const __half h2 = __float2half(p2), h3 = __float2half(p3);
                    const __half e0 = __float2half(p0 - __half2float(h0));
                    const __half e1 = __float2half(p1 - __half2float(h1));
                    const __half e2 = __float2half(p2 - __half2float(h2));
                    const __half e3 = __float2half(p3 - __half2float(h3));
                    const int pk = n >> 1, half = (n & 1) * 2;
                    aph[m][pk][half]     = hf2u(h0, h1);
                    aph[m][pk][half + 1] = hf2u(h2, h3);
                    apl[m][pk][half]     = hf2u(e0, e1);
                    apl[m][pk][half + 1] = hf2u(e2, e3);
                }
                s0 += __shfl_xor_sync(0xffffffffu, s0, 1);
                s0 += __shfl_xor_sync(0xffffffffu, s0, 2);
                s1 += __shfl_xor_sync(0xffffffffu, s1, 1);
                s1 += __shfl_xor_sync(0xffffffffu, s1, 2);
                l_s[m][0] = l_s[m][0] * cr0 + s0;
                l_s[m][1] = l_s[m][1] * cr1 + s1;
#pragma unroll
                for (int n = 0; n < 8; n++) {
                    c_o[m][n][0] *= cr0; c_o[m][n][1] *= cr0;
                    c_o[m][n][2] *= cr1; c_o[m][n][3] *= cr1;
                }
            }

#pragma unroll
            for (int pk = 0; pk < 2; pk++) {
                uint32_t vf[8][2];
#pragma unroll
                for (int jj = 0; jj < 4; jj++) {
                    const uint32_t off = swz128(
                        16 * pk + (lane & 7) + ((lane >> 3) & 1) * 8,
                        jj * 32 + ((lane >> 4) & 1) * 16);
                    uint32_t r[4];
                    ldsm_x4_t(r, kvb + 4096 + off);
                    vf[2 * jj][0] = r[0]; vf[2 * jj][1] = r[1];
                    vf[2 * jj + 1][0] = r[2]; vf[2 * jj + 1][1] = r[3];
                }
#pragma unroll
                for (int m = 0; m < 2; m++)
#pragma unroll
                    for (int n = 0; n < 8; n++) {
                        mma_f16(c_o[m][n], aph[m][pk], vf[n]);
                        mma_f16(c_o[m][n], apl[m][pk], vf[n]);
                    }
            }
        }
    }
#undef ISSUE_KV

    // ---- normalize + single fp16 write to g_af (B, S, D) ----
    const int bb = bh >> 4, hh = bh & (HEADS - 1);
#pragma unroll
    for (int m = 0; m < 2; m++) {
        const float i0 = 1.0f / l_s[m][0];
        const float i1 = 1.0f / l_s[m][1];
        const int r0 = qt * 128 + wid * 32 + m * 16 + gid;
        const int r1 = r0 + 8;
        const size_t a0 = ((size_t)bb * SEQ + r0) * DIM + hh * 64;
        const size_t a1 = ((size_t)bb * SEQ + r1) * DIM + hh * 64;
#pragma unroll
        for (int n = 0; n < 8; n++) {
            const int dcol = 8 * n + 2 * tq;
            *(uint32_t*)(g_af + a0 + dcol) =
                hf2u(__float2half(c_o[m][n][0] * i0), __float2half(c_o[m][n][1] * i0));
            *(uint32_t*)(g_af + a1 + dcol) =
                hf2u(__float2half(c_o[m][n][2] * i1), __float2half(c_o[m][n][3] * i1));
        }
    }
}

// ---------------------------------------------------------------------------
extern "C" void kernel_launch(void* const* d_in, const int* in_sizes, int n_in,
                              void* d_out, int out_size) {
    const float* query = 0;
    const float* W_qkv = 0;
    const float* b_qkv = 0;
    const float* W_out = 0;
    const float* b_out = 0;
    for (int i = 0; i < n_in; i++) {
        switch (in_sizes[i]) {
            case 4194304: query = (const float*)d_in[i]; break;
            case 3145728: W_qkv = (const float*)d_in[i]; break;
            case 3072:    b_qkv = (const float*)d_in[i]; break;
            case 1048576: W_out = (const float*)d_in[i]; break;
            case 1024:    b_out = (const float*)d_in[i]; break;
        }
    }
    float* out = (float*)d_out;

    cudaFuncSetAttribute(mma_gemm_kernel<0>, cudaFuncAttributeMaxDynamicSharedMemorySize, GSMEM);
    cudaFuncSetAttribute(mma_gemm_kernel<1>, cudaFuncAttributeMaxDynamicSharedMemorySize, GSMEM);
    cudaFuncSetAttribute(attn_mma_kernel, cudaFuncAttributeMaxDynamicSharedMemorySize, ATTN_SMEM);

    rope_table_kernel<<<(SEQ * 32 + 255) / 256, 256>>>();
    convert_x_kernel<<<NTOK * DIM / 1024, 256>>>(query);
    transpose_f16_kernel<<<dim3(QKV_N / 32 + DIM / 32, DIM / 32), dim3(32, 8)>>>(W_qkv, W_out);

    mma_gemm_kernel<0><<<dim3(QKV_N / 128, NTOK / 128), 256, GSMEM>>>(b_qkv, nullptr);

    attn_mma_kernel<<<dim3(BATCH * HEADS, SEQ / 128), 128, ATTN_SMEM>>>();

    mma_gemm_kernel<1><<<dim3(DIM / 128, NTOK / 128), 256, GSMEM>>>(b_out, out);
}

// round 16
// speedup vs baseline: 1.1120x; 1.1120x over previous
#include <cuda_runtime.h>
#include <cuda_bf16.h>
#include <cuda_fp16.h>
#include <math.h>
#include <stdint.h>

#define BATCH 2
#define SEQ   2048
#define DIM   1024
#define HEADS 16
#define HDIM  64
#define NTOK  (BATCH*SEQ)          // 4096
#define QKV_N (3*DIM)              // 3072

typedef unsigned long long u64;

// 0.125 * log2(e): folds attention scale + base-2 softmax into q
#define S0F 0.18033688011112042f

// ---- helpers (all base-PTX, no 'a' features) --------------------------------
__device__ __forceinline__ uint32_t s2u32(const void* p) {
    uint32_t a;
    asm("{ .reg .u64 t; cvta.to.shared.u64 t, %1; cvt.u32.u64 %0, t; }" : "=r"(a) : "l"(p));
    return a;
}
__device__ __forceinline__ void ldsm_x4(uint32_t* r, uint32_t addr) {
    asm volatile("ldmatrix.sync.aligned.m8n8.x4.shared.b16 {%0,%1,%2,%3}, [%4];"
                 : "=r"(r[0]), "=r"(r[1]), "=r"(r[2]), "=r"(r[3]) : "r"(addr));
}
__device__ __forceinline__ void ldsm_x4_t(uint32_t* r, uint32_t addr) {
    asm volatile("ldmatrix.sync.aligned.m8n8.x4.trans.shared.b16 {%0,%1,%2,%3}, [%4];"
                 : "=r"(r[0]), "=r"(r[1]), "=r"(r[2]), "=r"(r[3]) : "r"(addr));
}
__device__ __forceinline__ void mma_f16(float* c, const uint32_t* a, const uint32_t* b) {
    asm volatile(
        "mma.sync.aligned.m16n8k16.row.col.f32.f16.f16.f32 "
        "{%0,%1,%2,%3},{%4,%5,%6,%7},{%8,%9},{%0,%1,%2,%3};"
        : "+f"(c[0]), "+f"(c[1]), "+f"(c[2]), "+f"(c[3])
        : "r"(a[0]), "r"(a[1]), "r"(a[2]), "r"(a[3]), "r"(b[0]), "r"(b[1]));
}
__device__ __forceinline__ void cpa16(uint32_t dst, const void* src) {
    asm volatile("cp.async.cg.shared.global [%0], [%1], 16;" :: "r"(dst), "l"(src) : "memory");
}
#define CP_COMMIT() asm volatile("cp.async.commit_group;" ::: "memory")
#define CP_WAIT(n)  asm volatile("cp.async.wait_group %0;" :: "n"(n) : "memory")

__device__ __forceinline__ float ex2f(float x) {
    float r; asm("ex2.approx.f32 %0, %1;" : "=f"(r) : "f"(x)); return r;
}
__device__ __forceinline__ uint32_t hf2u(__half a, __half b) {
    __half2 t = __halves2half2(a, b);
    return *(uint32_t*)&t;
}

// SW64 swizzle for 64-byte rows (GEMM tiles, BK=32)
__device__ __forceinline__ uint32_t swzoff(int row, int kb) {
    return (uint32_t)(row * 64 + (kb ^ ((row & 6) << 3)));
}
// swizzle for 128-byte rows (attention tiles, 64 elems/row)
__device__ __forceinline__ uint32_t swz128(int row, int cb) {
    return (uint32_t)(row * 128 + (cb ^ ((row & 7) << 4)));
}

// ---- device scratch ----------------------------------------------------------
__device__ float g_cos[SEQ*32];
__device__ float g_sin[SEQ*32];
__device__ __half g_xf[NTOK*DIM];                          // fp16(X)
__device__ __half g_wqT[QKV_N*DIM];                        // fp16(W_qkv^T) (N,K)
__device__ __half g_woT[DIM*DIM];                          // fp16(W_out^T) (N,K)
__device__ __half g_qhi[BATCH*HEADS*SEQ*HDIM], g_qlo[BATCH*HEADS*SEQ*HDIM];
__device__ __half g_kf[BATCH*HEADS*SEQ*HDIM];              // single fp16 K
__device__ __half g_vf[BATCH*HEADS*SEQ*HDIM];              // single fp16 V
__device__ __half g_af[NTOK*DIM];                          // single fp16 attn out

// ---------------------------------------------------------------------------
// Fused prep kernel (one launch, blocks partitioned by task):
//   blocks [0,256):        RoPE table (fp64 sincos)
//   blocks [256,4352):     convert X fp32 -> fp16
//   blocks [4352,8448):    transpose W_qkv / W_out -> fp16 (N,K)
// ---------------------------------------------------------------------------
#define PREP_ROPE_BLKS 256
#define PREP_CVT_BLKS  4096
#define PREP_TR_BLKS   4096
#define PREP_BLKS      (PREP_ROPE_BLKS + PREP_CVT_BLKS + PREP_TR_BLKS)

__global__ __launch_bounds__(256) void prep_kernel(const float* __restrict__ X,
                                                   const float* __restrict__ Wq,
                                                   const float* __restrict__ Wo) {
    const int b = blockIdx.x;
    const int tid = threadIdx.x;

    if (b < PREP_ROPE_BLKS) {
        // ---- RoPE table ----
        const int idx = b * 256 + tid;                 // < 65536 = SEQ*32
        const int s = idx >> 5;
        const int j = idx & 31;
        double theta = (double)s * pow(10000.0, -(double)j / 32.0);
        double sc, cc;
        sincos(theta, &sc, &cc);
        g_cos[idx] = (float)cc;
        g_sin[idx] = (float)sc;
    } else if (b < PREP_ROPE_BLKS + PREP_CVT_BLKS) {
        // ---- convert X -> fp16 ----
        const int i = ((b - PREP_ROPE_BLKS) * 256 + tid) * 4;
        float4 v = *(const float4*)(X + i);
        *(uint32_t*)(g_xf + i)     = hf2u(__float2half(v.x), __float2half(v.y));
        *(uint32_t*)(g_xf + i + 2) = hf2u(__float2half(v.z), __float2half(v.w));
    } else {
        // ---- transpose weights -> fp16 (N,K) ----
        __shared__ float t32[32][33];
        const int tb = b - PREP_ROPE_BLKS - PREP_CVT_BLKS;   // 0..4095
        const int bxAll = tb & 127;                          // 0..127
        const int by    = tb >> 7;                           // 0..31
        const int which = (bxAll >= QKV_N / 32);
        const int bx = which ? (bxAll - QKV_N / 32) : bxAll;
        const int N = which ? DIM : QKV_N;
        const float* W = which ? Wo : Wq;
        __half* T = which ? g_woT : g_wqT;
        const int n0 = bx * 32, k0 = by * 32;
        const int tx = tid & 31, ty = tid >> 5;              // (32, 8)
#pragma unroll
        for (int i = 0; i < 4; i++)
            t32[ty + 8 * i][tx] = W[(size_t)(k0 + ty + 8 * i) * N + n0 + tx];
        __syncthreads();
#pragma unroll
        for (int i = 0; i < 4; i++) {
            float v = t32[tx][ty + 8 * i];
            T[(size_t)(n0 + ty + 8 * i) * DIM + k0 + tx] = __float2half(v);
        }
    }
}

// ---------------------------------------------------------------------------
// Warp-MMA fp16 GEMM (R11 frozen config): CTA 128x128, 8 warps (2x4),
// warp tile 64x32, BK=32, 4-stage cp.async, one sync per chunk, 2 CTAs/SM.
// MODE 0: fp16(X) @ W_qkv + bias, RoPE -> q split fp16 (scaled), k/v fp16
// MODE 1: fp16(attn) @ W_out + bias -> outp (fp32)
// ---------------------------------------------------------------------------
#define OFF_B   8192
#define BUF_SZ  16384
#define GSMEM   69632             // max(4*BUF_SZ=64K, 128*132*4=67.6K staging)

template<int MODE>
__global__ __launch_bounds__(256, 2) void mma_gemm_kernel(const float* __restrict__ bias,
                                                          float* __restrict__ outp) {
    extern __shared__ __align__(16) char sm[];
    const uint32_t smb = s2u32(sm);
    const int tid  = threadIdx.x;
    const int wid  = tid >> 5;
    const int lane = tid & 31;
    const int warp_m = wid >> 2;     // 0..1
    const int warp_n = wid & 3;      // 0..3

    const int n0 = blockIdx.x * 128;
    const int m0 = blockIdx.y * 128;

    const __half* __restrict__ Ah = (MODE == 0) ? g_xf : g_af;
    const __half* __restrict__ Bw = (MODE == 0) ? g_wqT : g_woT;

    float c[4][4][4];
#pragma unroll
    for (int i = 0; i < 4; i++)
#pragma unroll
        for (int j = 0; j < 4; j++)
#pragma unroll
            for (int r = 0; r < 4; r++) c[i][j][r] = 0.0f;

    const int ld_row = tid >> 2;          // 0..63
    const int ld_kb  = (tid & 3) * 16;

#define ISSUE_CHUNK(chunk, buf) do {                                           \
    const int k0e = (chunk) * 32;                                              \
    const uint32_t bb = smb + (buf) * BUF_SZ;                                  \
    _Pragma("unroll")                                                          \
    for (int m = 0; m < 2; m++) {                                              \
        const int row = ld_row + m * 64;                                       \
        const uint32_t so = swzoff(row, ld_kb);                                \
        cpa16(bb + so,         (const char*)(Ah + (size_t)(m0 + row) * DIM + k0e) + ld_kb); \
        cpa16(bb + OFF_B + so, (const char*)(Bw + (size_t)(n0 + row) * DIM + k0e) + ld_kb); \
    }                                                                          \
} while (0)

    ISSUE_CHUNK(0, 0); CP_COMMIT();
    ISSUE_CHUNK(1, 1); CP_COMMIT();
    ISSUE_CHUNK(2, 2); CP_COMMIT();

    for (int ch = 0; ch < 32; ch++) {
        if (ch <= 29) { CP_WAIT(2); }
        else if (ch == 30) { CP_WAIT(1); }
        else { CP_WAIT(0); }
        __syncthreads();
        if (ch + 3 < 32) {
            ISSUE_CHUNK(ch + 3, (ch + 3) & 3);
            CP_COMMIT();
        }

        const uint32_t bb = smb + (ch & 3) * BUF_SZ;
#pragma unroll
        for (int ks = 0; ks < 2; ks++) {
            uint32_t ah[4][4];
#pragma unroll
            for (int i = 0; i < 4; i++) {
                const int row = warp_m * 64 + 16 * i + (lane & 7) + ((lane >> 3) & 1) * 8;
                const int kb  = ks * 32 + (lane >> 4) * 16;
                ldsm_x4(ah[i], bb + swzoff(row, kb));
            }
            uint32_t bf[4][2];
#pragma unroll
            for (int j2 = 0; j2 < 2; j2++) {
                const int row = warp_n * 32 + 16 * j2 + (lane & 7) + ((lane >> 4) & 1) * 8;
                const int kb  = ks * 32 + ((lane >> 3) & 1) * 16;
                uint32_t r[4];
                ldsm_x4(r, bb + OFF_B + swzoff(row, kb));
                bf[2 * j2][0] = r[0]; bf[2 * j2][1] = r[1];
                bf[2 * j2 + 1][0] = r[2]; bf[2 * j2 + 1][1] = r[3];
            }
#pragma unroll
            for (int i = 0; i < 4; i++)
#pragma unroll
                for (int j = 0; j < 4; j++)
                    mma_f16(c[i][j], ah[i], bf[j]);
        }
    }
#undef ISSUE_CHUNK

    if (MODE == 1) {
#pragma unroll
        for (int i = 0; i < 4; i++) {
            const int row = m0 + warp_m * 64 + 16 * i + (lane >> 2);
#pragma unroll
            for (int j = 0; j < 4; j++) {
                const int col = n0 + warp_n * 32 + 8 * j + (lane & 3) * 2;
                const float b0 = bias[col], b1 = bias[col + 1];
                float2 v0 = make_float2(c[i][j][0] + b0, c[i][j][1] + b1);
                float2 v1 = make_float2(c[i][j][2] + b0, c[i][j][3] + b1);
                *(float2*)&outp[(size_t)row * DIM + col]       = v0;
                *(float2*)&outp[(size_t)(row + 8) * DIM + col] = v1;
            }
        }
        return;
    }

    // MODE 0: stage to smem so RoPE pairs (d, d+32) are in one thread
    __syncthreads();
    float* st = (float*)sm;                 // 128 rows x 132 stride
#pragma unroll
    for (int i = 0; i < 4; i++) {
        const int rl = warp_m * 64 + 16 * i + (lane >> 2);
#pragma unroll
        for (int j = 0; j < 4; j++) {
            const int cl = warp_n * 32 + 8 * j + (lane & 3) * 2;
            st[rl * 132 + cl]           = c[i][j][0];
            st[rl * 132 + cl + 1]       = c[i][j][1];
            st[(rl + 8) * 132 + cl]     = c[i][j][2];
            st[(rl + 8) * 132 + cl + 1] = c[i][j][3];
        }
    }
    __syncthreads();

    const int comp = n0 >> 10;               // 0=q 1=k 2=v
    const int r  = tid >> 1;
    const int hl = tid & 1;
    const int token = m0 + r;
    const int s  = token & (SEQ - 1);
    const int bb2 = token >> 11;
    const int gh = ((n0 + hl * 64) >> 6) & (HEADS - 1);
    const float* brow = bias + n0 + hl * 64;
    const float* srow = st + r * 132 + hl * 64;

    float vals[64];
    if (comp < 2) {
#pragma unroll
        for (int d = 0; d < 32; d++) {
            float x1 = srow[d]      + brow[d];
            float x2 = srow[32 + d] + brow[32 + d];
            float cs = g_cos[s * 32 + d], sn = g_sin[s * 32 + d];
            vals[d]      = x1 * cs - x2 * sn;
            vals[d + 32] = x2 * cs + x1 * sn;
        }
        if (comp == 0) {
#pragma unroll
            for (int j = 0; j < 64; j++) vals[j] *= S0F;
        }
    } else {
#pragma unroll
        for (int j = 0; j < 64; j++) vals[j] = srow[j] + brow[j];
    }

    const size_t base = (((size_t)bb2 * HEADS + gh) * SEQ + s) * HDIM;
    if (comp == 0) {
#pragma unroll
        for (int j2 = 0; j2 < 32; j2++) {
            float v0 = vals[2 * j2], v1 = vals[2 * j2 + 1];
            __half h0 = __float2half(v0), h1 = __float2half(v1);
            __half l0 = __float2half(v0 - __half2float(h0));
            __half l1 = __float2half(v1 - __half2float(h1));
            *(uint32_t*)(g_qhi + base + 2 * j2) = hf2u(h0, h1);
            *(uint32_t*)(g_qlo + base + 2 * j2) = hf2u(l0, l1);
        }
    } else {
        __half* df = (comp == 1) ? g_kf : g_vf;
#pragma unroll
        for (int j2 = 0; j2 < 32; j2++)
            *(uint32_t*)(df + base + 2 * j2) =
                hf2u(__float2half(vals[2 * j2]), __float2half(vals[2 * j2 + 1]));
    }
}

// ---------------------------------------------------------------------------
// MMA flash attention (R11 exact): grid (BH=32, QT=16), 128 threads
// (4 warps x 32 q-rows). 32-key tiles; QK = (qh+ql) x k_fp16;
// PV = (ph+pl) x v_fp16; base-2 softmax; causal; longest-first qt.
// Single fp16 output. smem: [0,16K) Qhi, [16K,32K) Qlo,
// bufs at 32K+b*8K: K +0, V +4096.
// ---------------------------------------------------------------------------
#define ATTN_SMEM 49152

__global__ __launch_bounds__(128) void attn_mma_kernel() {
    extern __shared__ __align__(16) char sm[];
    const uint32_t smb = s2u32(sm);
    const int bh = blockIdx.x;
    const int qt = (SEQ / 128 - 1) - blockIdx.y;     // longest-first scheduling
    const int tid = threadIdx.x, wid = tid >> 5, lane = tid & 31;
    const int gid = lane >> 2, tq = lane & 3;

    const __half* Qh = g_qhi + (size_t)bh * SEQ * HDIM;
    const __half* Ql = g_qlo + (size_t)bh * SEQ * HDIM;
    const __half* Kf = g_kf  + (size_t)bh * SEQ * HDIM;
    const __half* Vf = g_vf  + (size_t)bh * SEQ * HDIM;

    {
        const char* sh = (const char*)(Qh + (size_t)(qt * 128 + tid) * HDIM);
        const char* sl = (const char*)(Ql + (size_t)(qt * 128 + tid) * HDIM);
#pragma unroll
        for (int i = 0; i < 8; i++) {
            const uint32_t off = swz128(tid, i * 16);
            cpa16(smb + off, sh + i * 16);
            cpa16(smb + 16384 + off, sl + i * 16);
        }
    }
    CP_COMMIT();

    const int NT = 4 * qt + 4;

#define ISSUE_KV(t, b) do {                                                     \
    const int k0i = (t) * 32;                                                   \
    const uint32_t kb = smb + 32768 + (b) * 8192;                               \
    _Pragma("unroll")                                                           \
    for (int i = 0; i < 2; i++) {                                               \
        const int j = tid * 2 + i;                                              \
        const int rw = j >> 3, cbb = (j & 7) * 16;                              \
        const uint32_t off = swz128(rw, cbb);                                   \
        cpa16(kb + off,        (const char*)(Kf + (size_t)(k0i + rw) * HDIM) + cbb); \
        cpa16(kb + 4096 + off, (const char*)(Vf + (size_t)(k0i + rw) * HDIM) + cbb); \
    }                                                                           \
} while (0)

    ISSUE_KV(0, 0);
    CP_COMMIT();

    float c_o[2][8][4];
#pragma unroll
    for (int m = 0; m < 2; m++)
#pragma unroll
        for (int n = 0; n < 8; n++)
#pragma unroll
            for (int r = 0; r < 4; r++) c_o[m][n][r] = 0.0f;
    float m_s[2][2] = {{-1e30f, -1e30f}, {-1e30f, -1e30f}};
    float l_s[2][2] = {{0.0f, 0.0f}, {0.0f, 0.0f}};

    for (int t = 0; t < NT; t++) {
        const int buf = t & 1;
        CP_WAIT(0);
        __syncthreads();
        if (t + 1 < NT) {
            ISSUE_KV(t + 1, buf ^ 1);
            CP_COMMIT();
        }

        const bool active = (t <= 4 * qt + wid);
        if (active) {
            const uint32_t kvb = smb + 32768 + buf * 8192;

            float c_s[2][4][4];
#pragma unroll
            for (int m = 0; m < 2; m++)
#pragma unroll
                for (int n = 0; n < 4; n++)
#pragma unroll
                    for (int r = 0; r < 4; r++) c_s[m][n][r] = 0.0f;

#pragma unroll
            for (int ks = 0; ks < 4; ks++) {
                uint32_t qa[2][4], qb[2][4];
#pragma unroll
                for (int m = 0; m < 2; m++) {
                    const uint32_t off = swz128(
                        wid * 32 + m * 16 + (lane & 7) + ((lane >> 3) & 1) * 8,
                        ks * 32 + ((lane >> 4) & 1) * 16);
                    ldsm_x4(qa[m], smb + off);
                    ldsm_x4(qb[m], smb + 16384 + off);
                }
                uint32_t kf[4][2];
#pragma unroll
                for (int jj = 0; jj < 2; jj++) {
                    const uint32_t off = swz128(
                        16 * jj + (lane & 7) + ((lane >> 4) & 1) * 8,
                        ks * 32 + ((lane >> 3) & 1) * 16);
                    uint32_t r[4];
                    ldsm_x4(r, kvb + off);
                    kf[2 * jj][0] = r[0]; kf[2 * jj][1] = r[1];
                    kf[2 * jj + 1][0] = r[2]; kf[2 * jj + 1][1] = r[3];
                }
#pragma unroll
                for (int m = 0; m < 2; m++)
#pragma unroll
                    for (int n = 0; n < 4; n++) {
                        mma_f16(c_s[m][n], qa[m], kf[n]);
                        mma_f16(c_s[m][n], qb[m], kf[n]);
                    }
            }

            if (t == 4 * qt + wid) {
                const int k0 = t * 32;
                const int rbase = qt * 128 + wid * 32;
#pragma unroll
                for (int m = 0; m < 2; m++) {
                    const int r0 = rbase + m * 16 + gid, r1 = r0 + 8;
#pragma unroll
                    for (int n = 0; n < 4; n++) {
                        const int key = k0 + 8 * n + 2 * tq;
                        if (key     > r0) c_s[m][n][0] = -1e30f;
                        if (key + 1 > r0) c_s[m][n][1] = -1e30f;
                        if (key     > r1) c_s[m][n][2] = -1e30f;
                        if (key + 1 > r1) c_s[m][n][3] = -1e30f;
                    }
                }
            }

            uint32_t aph[2][2][4], apl[2][2][4];
#pragma unroll
            for (int m = 0; m < 2; m++) {
                float mx0 = -1e30f, mx1 = -1e30f;
#pragma unroll
                for (int n = 0; n < 4; n++) {
                    mx0 = fmaxf(mx0, fmaxf(c_s[m][n][0], c_s[m][n][1]));
                    mx1 = fmaxf(mx1, fmaxf(c_s[m][n][2], c_s[m][n][3]));
                }
                mx0 = fmaxf(mx0, __shfl_xor_sync(0xffffffffu, mx0, 1));
                mx0 = fmaxf(mx0, __shfl_xor_sync(0xffffffffu, mx0, 2));
                mx1 = fmaxf(mx1, __shfl_xor_sync(0xffffffffu, mx1, 1));
                mx1 = fmaxf(mx1, __shfl_xor_sync(0xffffffffu, mx1, 2));
                const float mn0 = fmaxf(m_s[m][0], mx0);
                const float mn1 = fmaxf(m_s[m][1], mx1);
                const float cr0 = ex2f(m_s[m][0] - mn0);
                const float cr1 = ex2f(m_s[m][1] - mn1);
                m_s[m][0] = mn0; m_s[m][1] = mn1;
                float s0 = 0.0f, s1 = 0.0f;
#pragma unroll
                for (int n = 0; n < 4; n++) {
                    const float p0 = ex2f(c_s[m][n][0] - mn0);
                    const float p1 = ex2f(c_s[m][n][1] - mn0);
                    const float p2 = ex2f(c_s[m][n][2] - mn1);
                    const float p3 = ex2f(c_s[m][n][3] - mn1);
                    s0 += p0 + p1; s1 += p2 + p3;
                    const __half h0 = __float2half(p0), h1 = __float2half(p1);
                    const __half h2 = __float2half(p2), h3 = __float2half(p3);
                    const __half e0 = __float2half(p0 - __half2float(h0));
                    const __half e1 = __float2half(p1 - __half2float(h1));
                    const __half e2 = __float2half(p2 - __half2float(h2));
                    const __half e3 = __float2half(p3 - __half2float(h3));
                    const int pk = n >> 1, half = (n & 1) * 2;
                    aph[m][pk][half]     = hf2u(h0, h1);
                    aph[m][pk][half + 1] = hf2u(h2, h3);
                    apl[m][pk][half]     = hf2u(e0, e1);
                    apl[m][pk][half + 1] = hf2u(e2, e3);
                }
                s0 += __shfl_xor_sync(0xffffffffu, s0, 1);
                s0 += __shfl_xor_sync(0xffffffffu, s0, 2);
                s1 += __shfl_xor_sync(0xffffffffu, s1, 1);
                s1 += __shfl_xor_sync(0xffffffffu, s1, 2);
                l_s[m][0] = l_s[m][0] * cr0 + s0;
                l_s[m][1] = l_s[m][1] * cr1 + s1;
#pragma unroll
                for (int n = 0; n < 8; n++) {
                    c_o[m][n][0] *= cr0; c_o[m][n][1] *= cr0;
                    c_o[m][n][2] *= cr1; c_o[m][n][3] *= cr1;
                }
            }

#pragma unroll
            for (int pk = 0; pk < 2; pk++) {
                uint32_t vf[8][2];
#pragma unroll
                for (int jj = 0; jj < 4; jj++) {
                    const uint32_t off = swz128(
                        16 * pk + (lane & 7) + ((lane >> 3) & 1) * 8,
                        jj * 32 + ((lane >> 4) & 1) * 16);
                    uint32_t r[4];
                    ldsm_x4_t(r, kvb + 4096 + off);
                    vf[2 * jj][0] = r[0]; vf[2 * jj][1] = r[1];
                    vf[2 * jj + 1][0] = r[2]; vf[2 * jj + 1][1] = r[3];
                }
#pragma unroll
                for (int m = 0; m < 2; m++)
#pragma unroll
                    for (int n = 0; n < 8; n++) {
                        mma_f16(c_o[m][n], aph[m][pk], vf[n]);
                        mma_f16(c_o[m][n], apl[m][pk], vf[n]);
                    }
            }
        }
    }
#undef ISSUE_KV

    // ---- normalize + single fp16 write to g_af (B, S, D) ----
    const int bb = bh >> 4, hh = bh & (HEADS - 1);
#pragma unroll
    for (int m = 0; m < 2; m++) {
        const float i0 = 1.0f / l_s[m][0];
        const float i1 = 1.0f / l_s[m][1];
        const int r0 = qt * 128 + wid * 32 + m * 16 + gid;
        const int r1 = r0 + 8;
        const size_t a0 = ((size_t)bb * SEQ + r0) * DIM + hh * 64;
        const size_t a1 = ((size_t)bb * SEQ + r1) * DIM + hh * 64;
#pragma unroll
        for (int n = 0; n < 8; n++) {
            const int dcol = 8 * n + 2 * tq;
            *(uint32_t*)(g_af + a0 + dcol) =
                hf2u(__float2half(c_o[m][n][0] * i0), __float2half(c_o[m][n][1] * i0));
            *(uint32_t*)(g_af + a1 + dcol) =
                hf2u(__float2half(c_o[m][n][2] * i1), __float2half(c_o[m][n][3] * i1));
        }
    }
}

// ---------------------------------------------------------------------------
extern "C" void kernel_launch(void* const* d_in, const int* in_sizes, int n_in,
                              void* d_out, int out_size) {
    const float* query = 0;
    const float* W_qkv = 0;
    const float* b_qkv = 0;
    const float* W_out = 0;
    const float* b_out = 0;
    for (int i = 0; i < n_in; i++) {
        switch (in_sizes[i]) {
            case 4194304: query = (const float*)d_in[i]; break;
            case 3145728: W_qkv = (const float*)d_in[i]; break;
            case 3072:    b_qkv = (const float*)d_in[i]; break;
            case 1048576: W_out = (const float*)d_in[i]; break;
            case 1024:    b_out = (const float*)d_in[i]; break;
        }
    }
    float* out = (float*)d_out;

    cudaFuncSetAttribute(mma_gemm_kernel<0>, cudaFuncAttributeMaxDynamicSharedMemorySize, GSMEM);
    cudaFuncSetAttribute(mma_gemm_kernel<1>, cudaFuncAttributeMaxDynamicSharedMemorySize, GSMEM);
    cudaFuncSetAttribute(attn_mma_kernel, cudaFuncAttributeMaxDynamicSharedMemorySize, ATTN_SMEM);

    prep_kernel<<<PREP_BLKS, 256>>>(query, W_qkv, W_out);

    mma_gemm_kernel<0><<<dim3(QKV_N / 128, NTOK / 128), 256, GSMEM>>>(b_qkv, nullptr);

    attn_mma_kernel<<<dim3(BATCH * HEADS, SEQ / 128), 128, ATTN_SMEM>>>();

    mma_gemm_kernel<1><<<dim3(DIM / 128, NTOK / 128), 256, GSMEM>>>(b_out, out);
}

// round 17
// speedup vs baseline: 1.1345x; 1.0202x over previous
#include <cuda_runtime.h>
#include <cuda_bf16.h>
#include <cuda_fp16.h>
#include <math.h>
#include <stdint.h>

#define BATCH 2
#define SEQ   2048
#define DIM   1024
#define HEADS 16
#define HDIM  64
#define NTOK  (BATCH*SEQ)          // 4096
#define QKV_N (3*DIM)              // 3072

typedef unsigned long long u64;

// 0.125 * log2(e): folds attention scale + base-2 softmax into q
#define S0F 0.18033688011112042f

// ---- helpers (all base-PTX, no 'a' features) --------------------------------
__device__ __forceinline__ uint32_t s2u32(const void* p) {
    uint32_t a;
    asm("{ .reg .u64 t; cvta.to.shared.u64 t, %1; cvt.u32.u64 %0, t; }" : "=r"(a) : "l"(p));
    return a;
}
__device__ __forceinline__ void ldsm_x4(uint32_t* r, uint32_t addr) {
    asm volatile("ldmatrix.sync.aligned.m8n8.x4.shared.b16 {%0,%1,%2,%3}, [%4];"
                 : "=r"(r[0]), "=r"(r[1]), "=r"(r[2]), "=r"(r[3]) : "r"(addr));
}
__device__ __forceinline__ void ldsm_x4_t(uint32_t* r, uint32_t addr) {
    asm volatile("ldmatrix.sync.aligned.m8n8.x4.trans.shared.b16 {%0,%1,%2,%3}, [%4];"
                 : "=r"(r[0]), "=r"(r[1]), "=r"(r[2]), "=r"(r[3]) : "r"(addr));
}
__device__ __forceinline__ void mma_f16(float* c, const uint32_t* a, const uint32_t* b) {
    asm volatile(
        "mma.sync.aligned.m16n8k16.row.col.f32.f16.f16.f32 "
        "{%0,%1,%2,%3},{%4,%5,%6,%7},{%8,%9},{%0,%1,%2,%3};"
        : "+f"(c[0]), "+f"(c[1]), "+f"(c[2]), "+f"(c[3])
        : "r"(a[0]), "r"(a[1]), "r"(a[2]), "r"(a[3]), "r"(b[0]), "r"(b[1]));
}
__device__ __forceinline__ void cpa16(uint32_t dst, const void* src) {
    asm volatile("cp.async.cg.shared.global [%0], [%1], 16;" :: "r"(dst), "l"(src) : "memory");
}
#define CP_COMMIT() asm volatile("cp.async.commit_group;" ::: "memory")
#define CP_WAIT(n)  asm volatile("cp.async.wait_group %0;" :: "n"(n) : "memory")

__device__ __forceinline__ float ex2f(float x) {
    float r; asm("ex2.approx.f32 %0, %1;" : "=f"(r) : "f"(x)); return r;
}
__device__ __forceinline__ uint32_t hf2u(__half a, __half b) {
    __half2 t = __halves2half2(a, b);
    return *(uint32_t*)&t;
}

// SW64 swizzle for 64-byte rows (GEMM tiles, BK=32)
__device__ __forceinline__ uint32_t swzoff(int row, int kb) {
    return (uint32_t)(row * 64 + (kb ^ ((row & 6) << 3)));
}
// swizzle for 128-byte rows (attention tiles, 64 elems/row)
__device__ __forceinline__ uint32_t swz128(int row, int cb) {
    return (uint32_t)(row * 128 + (cb ^ ((row & 7) << 4)));
}

// ---- device scratch ----------------------------------------------------------
__device__ float g_cos[SEQ*32];
__device__ float g_sin[SEQ*32];
__device__ __half g_xf[NTOK*DIM];                          // fp16(X)
__device__ __half g_wqT[QKV_N*DIM];                        // fp16(W_qkv^T) (N,K)
__device__ __half g_woT[DIM*DIM];                          // fp16(W_out^T) (N,K)
__device__ __half g_qhi[BATCH*HEADS*SEQ*HDIM], g_qlo[BATCH*HEADS*SEQ*HDIM];
__device__ __half g_kf[BATCH*HEADS*SEQ*HDIM];              // single fp16 K
__device__ __half g_vf[BATCH*HEADS*SEQ*HDIM];              // single fp16 V
__device__ __half g_af[NTOK*DIM];                          // single fp16 attn out

// ---------------------------------------------------------------------------
// Fused prep kernel (one launch, blocks partitioned by task):
//   blocks [0,256):        RoPE table (fp64 sincos)
//   blocks [256,4352):     convert X fp32 -> fp16
//   blocks [4352,8448):    transpose W_qkv / W_out -> fp16 (N,K)
// ---------------------------------------------------------------------------
#define PREP_ROPE_BLKS 256
#define PREP_CVT_BLKS  4096
#define PREP_TR_BLKS   4096
#define PREP_BLKS      (PREP_ROPE_BLKS + PREP_CVT_BLKS + PREP_TR_BLKS)

__global__ __launch_bounds__(256) void prep_kernel(const float* __restrict__ X,
                                                   const float* __restrict__ Wq,
                                                   const float* __restrict__ Wo) {
    const int b = blockIdx.x;
    const int tid = threadIdx.x;

    if (b < PREP_ROPE_BLKS) {
        const int idx = b * 256 + tid;                 // < 65536 = SEQ*32
        const int s = idx >> 5;
        const int j = idx & 31;
        double theta = (double)s * pow(10000.0, -(double)j / 32.0);
        double sc, cc;
        sincos(theta, &sc, &cc);
        g_cos[idx] = (float)cc;
        g_sin[idx] = (float)sc;
    } else if (b < PREP_ROPE_BLKS + PREP_CVT_BLKS) {
        const int i = ((b - PREP_ROPE_BLKS) * 256 + tid) * 4;
        float4 v = *(const float4*)(X + i);
        *(uint32_t*)(g_xf + i)     = hf2u(__float2half(v.x), __float2half(v.y));
        *(uint32_t*)(g_xf + i + 2) = hf2u(__float2half(v.z), __float2half(v.w));
    } else {
        __shared__ float t32[32][33];
        const int tb = b - PREP_ROPE_BLKS - PREP_CVT_BLKS;   // 0..4095
        const int bxAll = tb & 127;
        const int by    = tb >> 7;
        const int which = (bxAll >= QKV_N / 32);
        const int bx = which ? (bxAll - QKV_N / 32) : bxAll;
        const int N = which ? DIM : QKV_N;
        const float* W = which ? Wo : Wq;
        __half* T = which ? g_woT : g_wqT;
        const int n0 = bx * 32, k0 = by * 32;
        const int tx = tid & 31, ty = tid >> 5;              // (32, 8)
#pragma unroll
        for (int i = 0; i < 4; i++)
            t32[ty + 8 * i][tx] = W[(size_t)(k0 + ty + 8 * i) * N + n0 + tx];
        __syncthreads();
#pragma unroll
        for (int i = 0; i < 4; i++) {
            float v = t32[tx][ty + 8 * i];
            T[(size_t)(n0 + ty + 8 * i) * DIM + k0 + tx] = __float2half(v);
        }
    }
}

// ---------------------------------------------------------------------------
// Warp-MMA fp16 GEMM (R11 frozen config): CTA 128x128, 8 warps (2x4),
// warp tile 64x32, BK=32, 4-stage cp.async, one sync per chunk, 2 CTAs/SM.
// MODE 0: fp16(X) @ W_qkv + bias, RoPE -> q split fp16 (scaled), k/v fp16
// MODE 1: fp16(attn) @ W_out + bias -> outp (fp32)
// ---------------------------------------------------------------------------
#define OFF_B   8192
#define BUF_SZ  16384
#define GSMEM   69632             // max(4*BUF_SZ=64K, 128*132*4=67.6K staging)

template<int MODE>
__global__ __launch_bounds__(256, 2) void mma_gemm_kernel(const float* __restrict__ bias,
                                                          float* __restrict__ outp) {
    extern __shared__ __align__(16) char sm[];
    const uint32_t smb = s2u32(sm);
    const int tid  = threadIdx.x;
    const int wid  = tid >> 5;
    const int lane = tid & 31;
    const int warp_m = wid >> 2;     // 0..1
    const int warp_n = wid & 3;      // 0..3

    const int n0 = blockIdx.x * 128;
    const int m0 = blockIdx.y * 128;

    const __half* __restrict__ Ah = (MODE == 0) ? g_xf : g_af;
    const __half* __restrict__ Bw = (MODE == 0) ? g_wqT : g_woT;

    float c[4][4][4];
#pragma unroll
    for (int i = 0; i < 4; i++)
#pragma unroll
        for (int j = 0; j < 4; j++)
#pragma unroll
            for (int r = 0; r < 4; r++) c[i][j][r] = 0.0f;

    const int ld_row = tid >> 2;          // 0..63
    const int ld_kb  = (tid & 3) * 16;

#define ISSUE_CHUNK(chunk, buf) do {                                           \
    const int k0e = (chunk) * 32;                                              \
    const uint32_t bb = smb + (buf) * BUF_SZ;                                  \
    _Pragma("unroll")                                                          \
    for (int m = 0; m < 2; m++) {                                              \
        const int row = ld_row + m * 64;                                       \
        const uint32_t so = swzoff(row, ld_kb);                                \
        cpa16(bb + so,         (const char*)(Ah + (size_t)(m0 + row) * DIM + k0e) + ld_kb); \
        cpa16(bb + OFF_B + so, (const char*)(Bw + (size_t)(n0 + row) * DIM + k0e) + ld_kb); \
    }                                                                          \
} while (0)

    ISSUE_CHUNK(0, 0); CP_COMMIT();
    ISSUE_CHUNK(1, 1); CP_COMMIT();
    ISSUE_CHUNK(2, 2); CP_COMMIT();

    for (int ch = 0; ch < 32; ch++) {
        if (ch <= 29) { CP_WAIT(2); }
        else if (ch == 30) { CP_WAIT(1); }
        else { CP_WAIT(0); }
        __syncthreads();
        if (ch + 3 < 32) {
            ISSUE_CHUNK(ch + 3, (ch + 3) & 3);
            CP_COMMIT();
        }

        const uint32_t bb = smb + (ch & 3) * BUF_SZ;
#pragma unroll
        for (int ks = 0; ks < 2; ks++) {
            uint32_t ah[4][4];
#pragma unroll
            for (int i = 0; i < 4; i++) {
                const int row = warp_m * 64 + 16 * i + (lane & 7) + ((lane >> 3) & 1) * 8;
                const int kb  = ks * 32 + (lane >> 4) * 16;
                ldsm_x4(ah[i], bb + swzoff(row, kb));
            }
            uint32_t bf[4][2];
#pragma unroll
            for (int j2 = 0; j2 < 2; j2++) {
                const int row = warp_n * 32 + 16 * j2 + (lane & 7) + ((lane >> 4) & 1) * 8;
                const int kb  = ks * 32 + ((lane >> 3) & 1) * 16;
                uint32_t r[4];
                ldsm_x4(r, bb + OFF_B + swzoff(row, kb));
                bf[2 * j2][0] = r[0]; bf[2 * j2][1] = r[1];
                bf[2 * j2 + 1][0] = r[2]; bf[2 * j2 + 1][1] = r[3];
            }
#pragma unroll
            for (int i = 0; i < 4; i++)
#pragma unroll
                for (int j = 0; j < 4; j++)
                    mma_f16(c[i][j], ah[i], bf[j]);
        }
    }
#undef ISSUE_CHUNK

    if (MODE == 1) {
#pragma unroll
        for (int i = 0; i < 4; i++) {
            const int row = m0 + warp_m * 64 + 16 * i + (lane >> 2);
#pragma unroll
            for (int j = 0; j < 4; j++) {
                const int col = n0 + warp_n * 32 + 8 * j + (lane & 3) * 2;
                const float b0 = bias[col], b1 = bias[col + 1];
                float2 v0 = make_float2(c[i][j][0] + b0, c[i][j][1] + b1);
                float2 v1 = make_float2(c[i][j][2] + b0, c[i][j][3] + b1);
                *(float2*)&outp[(size_t)row * DIM + col]       = v0;
                *(float2*)&outp[(size_t)(row + 8) * DIM + col] = v1;
            }
        }
        return;
    }

    // MODE 0: stage to smem so RoPE pairs (d, d+32) are in one thread
    __syncthreads();
    float* st = (float*)sm;                 // 128 rows x 132 stride
#pragma unroll
    for (int i = 0; i < 4; i++) {
        const int rl = warp_m * 64 + 16 * i + (lane >> 2);
#pragma unroll
        for (int j = 0; j < 4; j++) {
            const int cl = warp_n * 32 + 8 * j + (lane & 3) * 2;
            st[rl * 132 + cl]           = c[i][j][0];
            st[rl * 132 + cl + 1]       = c[i][j][1];
            st[(rl + 8) * 132 + cl]     = c[i][j][2];
            st[(rl + 8) * 132 + cl + 1] = c[i][j][3];
        }
    }
    __syncthreads();

    const int comp = n0 >> 10;               // 0=q 1=k 2=v
    const int r  = tid >> 1;
    const int hl = tid & 1;
    const int token = m0 + r;
    const int s  = token & (SEQ - 1);
    const int bb2 = token >> 11;
    const int gh = ((n0 + hl * 64) >> 6) & (HEADS - 1);
    const float* brow = bias + n0 + hl * 64;
    const float* srow = st + r * 132 + hl * 64;

    float vals[64];
    if (comp < 2) {
#pragma unroll
        for (int d = 0; d < 32; d++) {
            float x1 = srow[d]      + brow[d];
            float x2 = srow[32 + d] + brow[32 + d];
            float cs = g_cos[s * 32 + d], sn = g_sin[s * 32 + d];
            vals[d]      = x1 * cs - x2 * sn;
            vals[d + 32] = x2 * cs + x1 * sn;
        }
        if (comp == 0) {
#pragma unroll
            for (int j = 0; j < 64; j++) vals[j] *= S0F;
        }
    } else {
#pragma unroll
        for (int j = 0; j < 64; j++) vals[j] = srow[j] + brow[j];
    }

    const size_t base = (((size_t)bb2 * HEADS + gh) * SEQ + s) * HDIM;
    if (comp == 0) {
#pragma unroll
        for (int j2 = 0; j2 < 32; j2++) {
            float v0 = vals[2 * j2], v1 = vals[2 * j2 + 1];
            __half h0 = __float2half(v0), h1 = __float2half(v1);
            __half l0 = __float2half(v0 - __half2float(h0));
            __half l1 = __float2half(v1 - __half2float(h1));
            *(uint32_t*)(g_qhi + base + 2 * j2) = hf2u(h0, h1);
            *(uint32_t*)(g_qlo + base + 2 * j2) = hf2u(l0, l1);
        }
    } else {
        __half* df = (comp == 1) ? g_kf : g_vf;
#pragma unroll
        for (int j2 = 0; j2 < 32; j2++)
            *(uint32_t*)(df + base + 2 * j2) =
                hf2u(__float2half(vals[2 * j2]), __float2half(vals[2 * j2 + 1]));
    }
}

// ---------------------------------------------------------------------------
// MMA flash attention (R16 + single-fp16 P): grid (BH=32, QT=16), 128 threads
// (4 warps x 32 q-rows). 32-key tiles; QK = (qh+ql) x k_fp16;
// PV = p_fp16 x v_fp16 (single term); base-2 softmax; causal;
// longest-first qt. Single fp16 output.
// smem: [0,16K) Qhi, [16K,32K) Qlo, bufs at 32K+b*8K: K +0, V +4096.
// ---------------------------------------------------------------------------
#define ATTN_SMEM 49152

__global__ __launch_bounds__(128) void attn_mma_kernel() {
    extern __shared__ __align__(16) char sm[];
    const uint32_t smb = s2u32(sm);
    const int bh = blockIdx.x;
    const int qt = (SEQ / 128 - 1) - blockIdx.y;     // longest-first scheduling
    const int tid = threadIdx.x, wid = tid >> 5, lane = tid & 31;
    const int gid = lane >> 2, tq = lane & 3;

    const __half* Qh = g_qhi + (size_t)bh * SEQ * HDIM;
    const __half* Ql = g_qlo + (size_t)bh * SEQ * HDIM;
    const __half* Kf = g_kf  + (size_t)bh * SEQ * HDIM;
    const __half* Vf = g_vf  + (size_t)bh * SEQ * HDIM;

    {
        const char* sh = (const char*)(Qh + (size_t)(qt * 128 + tid) * HDIM);
        const char* sl = (const char*)(Ql + (size_t)(qt * 128 + tid) * HDIM);
#pragma unroll
        for (int i = 0; i < 8; i++) {
            const uint32_t off = swz128(tid, i * 16);
            cpa16(smb + off, sh + i * 16);
            cpa16(smb + 16384 + off, sl + i * 16);
        }
    }
    CP_COMMIT();

    const int NT = 4 * qt + 4;

#define ISSUE_KV(t, b) do {                                                     \
    const int k0i = (t) * 32;                                                   \
    const uint32_t kb = smb + 32768 + (b) * 8192;                               \
    _Pragma("unroll")                                                           \
    for (int i = 0; i < 2; i++) {                                               \
        const int j = tid * 2 + i;                                              \
        const int rw = j >> 3, cbb = (j & 7) * 16;                              \
        const uint32_t off = swz128(rw, cbb);                                   \
        cpa16(kb + off,        (const char*)(Kf + (size_t)(k0i + rw) * HDIM) + cbb); \
        cpa16(kb + 4096 + off, (const char*)(Vf + (size_t)(k0i + rw) * HDIM) + cbb); \
    }                                                                           \
} while (0)

    ISSUE_KV(0, 0);
    CP_COMMIT();

    float c_o[2][8][4];
#pragma unroll
    for (int m = 0; m < 2; m++)
#pragma unroll
        for (int n = 0; n < 8; n++)
#pragma unroll
            for (int r = 0; r < 4; r++) c_o[m][n][r] = 0.0f;
    float m_s[2][2] = {{-1e30f, -1e30f}, {-1e30f, -1e30f}};
    float l_s[2][2] = {{0.0f, 0.0f}, {0.0f, 0.0f}};

    for (int t = 0; t < NT; t++) {
        const int buf = t & 1;
        CP_WAIT(0);
        __syncthreads();
        if (t + 1 < NT) {
            ISSUE_KV(t + 1, buf ^ 1);
            CP_COMMIT();
        }

        const bool active = (t <= 4 * qt + wid);
        if (active) {
            const uint32_t kvb = smb + 32768 + buf * 8192;

            float c_s[2][4][4];
#pragma unroll
            for (int m = 0; m < 2; m++)
#pragma unroll
                for (int n = 0; n < 4; n++)
#pragma unroll
                    for (int r = 0; r < 4; r++) c_s[m][n][r] = 0.0f;

#pragma unroll
            for (int ks = 0; ks < 4; ks++) {
                uint32_t qa[2][4], qb[2][4];
#pragma unroll
                for (int m = 0; m < 2; m++) {
                    const uint32_t off = swz128(
                        wid * 32 + m * 16 + (lane & 7) + ((lane >> 3) & 1) * 8,
                        ks * 32 + ((lane >> 4) & 1) * 16);
                    ldsm_x4(qa[m], smb + off);
                    ldsm_x4(qb[m], smb + 16384 + off);
                }
                uint32_t kf[4][2];
#pragma unroll
                for (int jj = 0; jj < 2; jj++) {
                    const uint32_t off = swz128(
                        16 * jj + (lane & 7) + ((lane >> 4) & 1) * 8,
                        ks * 32 + ((lane >> 3) & 1) * 16);
                    uint32_t r[4];
                    ldsm_x4(r, kvb + off);
                    kf[2 * jj][0] = r[0]; kf[2 * jj][1] = r[1];
                    kf[2 * jj + 1][0] = r[2]; kf[2 * jj + 1][1] = r[3];
                }
#pragma unroll
                for (int m = 0; m < 2; m++)
#pragma unroll
                    for (int n = 0; n < 4; n++) {
                        mma_f16(c_s[m][n], qa[m], kf[n]);
                        mma_f16(c_s[m][n], qb[m], kf[n]);
                    }
            }

            if (t == 4 * qt + wid) {
                const int k0 = t * 32;
                const int rbase = qt * 128 + wid * 32;
#pragma unroll
                for (int m = 0; m < 2; m++) {
                    const int r0 = rbase + m * 16 + gid, r1 = r0 + 8;
#pragma unroll
                    for (int n = 0; n < 4; n++) {
                        const int key = k0 + 8 * n + 2 * tq;
                        if (key     > r0) c_s[m][n][0] = -1e30f;
                        if (key + 1 > r0) c_s[m][n][1] = -1e30f;
                        if (key     > r1) c_s[m][n][2] = -1e30f;
                        if (key + 1 > r1) c_s[m][n][3] = -1e30f;
                    }
                }
            }

            uint32_t aph[2][2][4];
#pragma unroll
            for (int m = 0; m < 2; m++) {
                float mx0 = -1e30f, mx1 = -1e30f;
#pragma unroll
                for (int n = 0; n < 4; n++) {
                    mx0 = fmaxf(mx0, fmaxf(c_s[m][n][0], c_s[m][n][1]));
                    mx1 = fmaxf(mx1, fmaxf(c_s[m][n][2], c_s[m][n][3]));
                }
                mx0 = fmaxf(mx0, __shfl_xor_sync(0xffffffffu, mx0, 1));
                mx0 = fmaxf(mx0, __shfl_xor_sync(0xffffffffu, mx0, 2));
                mx1 = fmaxf(mx1, __shfl_xor_sync(0xffffffffu, mx1, 1));
                mx1 = fmaxf(mx1, __shfl_xor_sync(0xffffffffu, mx1, 2));
                const float mn0 = fmaxf(m_s[m][0], mx0);
                const float mn1 = fmaxf(m_s[m][1], mx1);
                const float cr0 = ex2f(m_s[m][0] - mn0);
                const float cr1 = ex2f(m_s[m][1] - mn1);
                m_s[m][0] = mn0; m_s[m][1] = mn1;
                float s0 = 0.0f, s1 = 0.0f;
#pragma unroll
                for (int n = 0; n < 4; n++) {
                    const float p0 = ex2f(c_s[m][n][0] - mn0);
                    const float p1 = ex2f(c_s[m][n][1] - mn0);
                    const float p2 = ex2f(c_s[m][n][2] - mn1);
                    const float p3 = ex2f(c_s[m][n][3] - mn1);
                    s0 += p0 + p1; s1 += p2 + p3;
                    const int pk = n >> 1, half = (n & 1) * 2;
                    aph[m][pk][half]     = hf2u(__float2half(p0), __float2half(p1));
                    aph[m][pk][half + 1] = hf2u(__float2half(p2), __float2half(p3));
                }
                s0 += __shfl_xor_sync(0xffffffffu, s0, 1);
                s0 += __shfl_xor_sync(0xffffffffu, s0, 2);
                s1 += __shfl_xor_sync(0xffffffffu, s1, 1);
                s1 += __shfl_xor_sync(0xffffffffu, s1, 2);
                l_s[m][0] = l_s[m][0] * cr0 + s0;
                l_s[m][1] = l_s[m][1] * cr1 + s1;
#pragma unroll
                for (int n = 0; n < 8; n++) {
                    c_o[m][n][0] *= cr0; c_o[m][n][1] *= cr0;
                    c_o[m][n][2] *= cr1; c_o[m][n][3] *= cr1;
                }
            }

#pragma unroll
            for (int pk = 0; pk < 2; pk++) {
                uint32_t vf[8][2];
#pragma unroll
                for (int jj = 0; jj < 4; jj++) {
                    const uint32_t off = swz128(
                        16 * pk + (lane & 7) + ((lane >> 3) & 1) * 8,
                        jj * 32 + ((lane >> 4) & 1) * 16);
                    uint32_t r[4];
                    ldsm_x4_t(r, kvb + 4096 + off);
                    vf[2 * jj][0] = r[0]; vf[2 * jj][1] = r[1];
                    vf[2 * jj + 1][0] = r[2]; vf[2 * jj + 1][1] = r[3];
                }
#pragma unroll
                for (int m = 0; m < 2; m++)
#pragma unroll
                    for (int n = 0; n < 8; n++)
                        mma_f16(c_o[m][n], aph[m][pk], vf[n]);
            }
        }
    }
#undef ISSUE_KV

    // ---- normalize + single fp16 write to g_af (B, S, D) ----
    const int bb = bh >> 4, hh = bh & (HEADS - 1);
#pragma unroll
    for (int m = 0; m < 2; m++) {
        const float i0 = 1.0f / l_s[m][0];
        const float i1 = 1.0f / l_s[m][1];
        const int r0 = qt * 128 + wid * 32 + m * 16 + gid;
        const int r1 = r0 + 8;
        const size_t a0 = ((size_t)bb * SEQ + r0) * DIM + hh * 64;
        const size_t a1 = ((size_t)bb * SEQ + r1) * DIM + hh * 64;
#pragma unroll
        for (int n = 0; n < 8; n++) {
            const int dcol = 8 * n + 2 * tq;
            *(uint32_t*)(g_af + a0 + dcol) =
                hf2u(__float2half(c_o[m][n][0] * i0), __float2half(c_o[m][n][1] * i0));
            *(uint32_t*)(g_af + a1 + dcol) =
                hf2u(__float2half(c_o[m][n][2] * i1), __float2half(c_o[m][n][3] * i1));
        }
    }
}

// ---------------------------------------------------------------------------
extern "C" void kernel_launch(void* const* d_in, const int* in_sizes, int n_in,
                              void* d_out, int out_size) {
    const float* query = 0;
    const float* W_qkv = 0;
    const float* b_qkv = 0;
    const float* W_out = 0;
    const float* b_out = 0;
    for (int i = 0; i < n_in; i++) {
        switch (in_sizes[i]) {
            case 4194304: query = (const float*)d_in[i]; break;
            case 3145728: W_qkv = (const float*)d_in[i]; break;
            case 3072:    b_qkv = (const float*)d_in[i]; break;
            case 1048576: W_out = (const float*)d_in[i]; break;
            case 1024:    b_out = (const float*)d_in[i]; break;
        }
    }
    float* out = (float*)d_out;

    cudaFuncSetAttribute(mma_gemm_kernel<0>, cudaFuncAttributeMaxDynamicSharedMemorySize, GSMEM);
    cudaFuncSetAttribute(mma_gemm_kernel<1>, cudaFuncAttributeMaxDynamicSharedMemorySize, GSMEM);
    cudaFuncSetAttribute(attn_mma_kernel, cudaFuncAttributeMaxDynamicSharedMemorySize, ATTN_SMEM);

    prep_kernel<<<PREP_BLKS, 256>>>(query, W_qkv, W_out);

    mma_gemm_kernel<0><<<dim3(QKV_N / 128, NTOK / 128), 256, GSMEM>>>(b_qkv, nullptr);

    attn_mma_kernel<<<dim3(BATCH * HEADS, SEQ / 128), 128, ATTN_SMEM>>>();

    mma_gemm_kernel<1><<<dim3(DIM / 128, NTOK / 128), 256, GSMEM>>>(b_out, out);
}